// round 7
// baseline (speedup 1.0000x reference)
#include <cuda_runtime.h>
#include <cuda_bf16.h>

// MoE gather-combine: out[t, :] = sum_k scores[t*K+k] * flat[slots[t*K+k], :]
// 1 CTA per token, 256 threads. Each thread covers 8 contiguous floats of
// the row with a single 256-bit LDG (ld.global.nc.L2::evict_last.v8.b32 —
// the sm_103a-sanctioned v8 form). 2 rows (K=2) = 2 LDG.256/thread, so a
// warp requests 1KB (8 full 128B lines) per instruction: fewer L1tex
// wavefronts, larger ordered DRAM read bursts against the mixed r/w stream.
// Output stored with .cs (streaming, never re-read).

struct F8 { float v[8]; };

__device__ __forceinline__ F8 ldg_v8(const float* p) {
    unsigned r0, r1, r2, r3, r4, r5, r6, r7;
    asm volatile(
        "ld.global.nc.L2::evict_last.v8.b32 {%0,%1,%2,%3,%4,%5,%6,%7}, [%8];"
        : "=r"(r0), "=r"(r1), "=r"(r2), "=r"(r3),
          "=r"(r4), "=r"(r5), "=r"(r6), "=r"(r7)
        : "l"(p));
    F8 o;
    o.v[0] = __uint_as_float(r0); o.v[1] = __uint_as_float(r1);
    o.v[2] = __uint_as_float(r2); o.v[3] = __uint_as_float(r3);
    o.v[4] = __uint_as_float(r4); o.v[5] = __uint_as_float(r5);
    o.v[6] = __uint_as_float(r6); o.v[7] = __uint_as_float(r7);
    return o;
}

__device__ __forceinline__ void stcs_f4(float* p, float x, float y, float z, float w) {
    asm volatile("st.global.cs.v4.f32 [%0], {%1,%2,%3,%4};"
                 :: "l"(p), "f"(x), "f"(y), "f"(z), "f"(w) : "memory");
}

__global__ void __launch_bounds__(256, 8)
moe_gather_h2048_kernel(const float* __restrict__ flat,
                        const float* __restrict__ scores,
                        const int* __restrict__ slots,
                        const int* __restrict__ topk_p,
                        float* __restrict__ out,
                        int n_tokens) {
    const int token = blockIdx.x;
    if (token >= n_tokens) return;
    const int K = topk_p[0];

    const int off = threadIdx.x * 8;               // 8 floats per thread
    float* op = out + (size_t)token * 2048 + off;

    if (K == 2) {
        const int   s0 = __ldg(&slots[token * 2 + 0]);
        const int   s1 = __ldg(&slots[token * 2 + 1]);
        const float w0 = __ldg(&scores[token * 2 + 0]);
        const float w1 = __ldg(&scores[token * 2 + 1]);

        // Two independent 256-bit loads, both in flight before any FMA.
        F8 a = ldg_v8(flat + (size_t)s0 * 2048 + off);
        F8 b = ldg_v8(flat + (size_t)s1 * 2048 + off);

        float r[8];
        #pragma unroll
        for (int j = 0; j < 8; ++j)
            r[j] = fmaf(w1, b.v[j], w0 * a.v[j]);

        stcs_f4(op + 0, r[0], r[1], r[2], r[3]);
        stcs_f4(op + 4, r[4], r[5], r[6], r[7]);
        return;
    }

    // Generic K path.
    float r[8];
    #pragma unroll
    for (int j = 0; j < 8; ++j) r[j] = 0.f;
    for (int k = 0; k < K; ++k) {
        const int   slot = __ldg(&slots[token * K + k]);
        const float w    = __ldg(&scores[token * K + k]);
        F8 a = ldg_v8(flat + (size_t)slot * 2048 + off);
        #pragma unroll
        for (int j = 0; j < 8; ++j)
            r[j] = fmaf(w, a.v[j], r[j]);
    }
    stcs_f4(op + 0, r[0], r[1], r[2], r[3]);
    stcs_f4(op + 4, r[4], r[5], r[6], r[7]);
}

// Generic fallback for any hidden (scalar loop within row).
__global__ void moe_gather_generic_kernel(const float* __restrict__ flat,
                                          const float* __restrict__ scores,
                                          const int* __restrict__ slots,
                                          const int* __restrict__ topk_p,
                                          float* __restrict__ out,
                                          int n_tokens, int hidden) {
    const int token = blockIdx.x;
    if (token >= n_tokens) return;
    const int K = topk_p[0];

    for (int h = threadIdx.x; h < hidden; h += blockDim.x) {
        float acc = 0.f;
        for (int k = 0; k < K; ++k) {
            const int   slot = slots[token * K + k];
            const float w    = scores[token * K + k];
            acc = fmaf(w, flat[(size_t)slot * hidden + h], acc);
        }
        out[(size_t)token * hidden + h] = acc;
    }
}

extern "C" void kernel_launch(void* const* d_in, const int* in_sizes, int n_in,
                              void* d_out, int out_size) {
    const float* flat   = (const float*)d_in[0];   // moe_output, [n_slots, hidden]
    const float* scores = (const float*)d_in[1];   // [n_slots]
    const int*   slots  = (const int*)d_in[2];     // [n_slots]
    const int*   topk_p = (const int*)d_in[3];     // scalar top_k (device)

    const int n_slots = in_sizes[1];
    const int hidden  = in_sizes[0] / n_slots;
    const int n_tokens = out_size / hidden;

    float* out = (float*)d_out;

    if (hidden == 2048) {
        moe_gather_h2048_kernel<<<n_tokens, 256>>>(flat, scores, slots, topk_p,
                                                   out, n_tokens);
    } else {
        moe_gather_generic_kernel<<<n_tokens, 256>>>(flat, scores, slots, topk_p,
                                                     out, n_tokens, hidden);
    }
}